// round 3
// baseline (speedup 1.0000x reference)
#include <cuda_runtime.h>
#include <cuda_bf16.h>
#include <cstdint>

#define D_MODEL 1024
#define NUM_T   2048
#define BATCH   32

#define PE_ELEMS (NUM_T * D_MODEL)            // 2,097,152
#define PE_VEC4  (PE_ELEMS / 4)               // 524,288
#define DVEC     (D_MODEL / 4)                // 256

// -2/D * log2(10000):  angle = t * 2^(i * NEG_EXP_SCALE)
#define LOG2_10000 13.287712379549449f

// Fused kernel: one thread per unique (t, d-vec4) PE position.
// Compute 4 PE values once, then broadcast-add across all 32 batches.
// The transcendental work (~2M sincos total) hides under the DRAM-bound
// batch loop (issue util was only 11%).
__global__ void __launch_bounds__(256) fused_pe_add_kernel(const float4* __restrict__ x,
                                                           float4* __restrict__ out) {
    const unsigned pos = blockIdx.x * blockDim.x + threadIdx.x;   // 0..PE_VEC4-1
    const int dvec = pos & (DVEC - 1);        // d-vec4 index 0..255
    const int t    = pos >> 8;                // timestep 0..2047
    const float ft = (float)t;
    const int i0   = dvec * 4;                // first column (even)

    // inv_i = 10000^(-2*i/D) = 2^(-2*i/D * log2(10000))
    const float k = -2.0f / (float)D_MODEL * LOG2_10000;
    float a0 = ft * exp2f((float)(i0 + 0) * k);
    float a1 = ft * exp2f((float)(i0 + 1) * k);
    float a2 = ft * exp2f((float)(i0 + 2) * k);
    float a3 = ft * exp2f((float)(i0 + 3) * k);

    float4 pe;
    pe.x = sinf(a0);   // even i -> sin
    pe.y = cosf(a1);   // odd  i -> cos
    pe.z = sinf(a2);
    pe.w = cosf(a3);

    // Broadcast over batches: x/out strides of PE_VEC4 vec4s (8 MB)
    #pragma unroll 8
    for (int b = 0; b < BATCH; b++) {
        unsigned idx = pos + (unsigned)b * PE_VEC4;
        float4 xv = __ldcs(&x[idx]);          // streaming read (no reuse)
        float4 o;
        o.x = xv.x + pe.x;
        o.y = xv.y + pe.y;
        o.z = xv.z + pe.z;
        o.w = xv.w + pe.w;
        __stcs(&out[idx], o);                 // streaming write
    }
}

extern "C" void kernel_launch(void* const* d_in, const int* in_sizes, int n_in,
                              void* d_out, int out_size) {
    const float4* x = (const float4*)d_in[0];
    float4* out = (float4*)d_out;
    // 524288 threads = 2048 blocks of 256; exact cover, no tail
    fused_pe_add_kernel<<<PE_VEC4 / 256, 256>>>(x, out);
}

// round 4
// speedup vs baseline: 1.0497x; 1.0497x over previous
#include <cuda_runtime.h>
#include <cuda_bf16.h>
#include <cstdint>

#define D_MODEL 1024
#define NUM_T   2048
#define BATCH   32

#define PE_ELEMS (NUM_T * D_MODEL)            // 2,097,152
#define PE_VEC4  (PE_ELEMS / 4)               // 524,288
#define DVEC     (D_MODEL / 4)                // 256

#define BPT     8                             // batches per thread
#define GROUPS  (BATCH / BPT)                 // 4 block-groups

#define LOG2_10000 13.287712379549449f

// Fused PE+add. One thread = one unique (t, d-vec4) position x 8 batches.
// 4 block-groups (interleaved via low blockIdx bits) split the 32 batches,
// so concurrent blocks form 4 contiguous streams — the pattern that hit
// 81.6% DRAM in round 2 — while PE compute (4x redundant, ~17% fma) hides
// under the memory stream and the PE L2 read traffic (256 MB) vanishes.
__global__ void __launch_bounds__(256) fused_pe_add_kernel(const float4* __restrict__ x,
                                                           float4* __restrict__ out) {
    const unsigned g   = blockIdx.x & (GROUPS - 1u);      // batch group 0..3
    const unsigned pb  = blockIdx.x >> 2;                 // position block 0..2047
    const unsigned pos = pb * 256u + threadIdx.x;         // 0..PE_VEC4-1

    const int t  = pos >> 8;                  // timestep 0..2047
    const int i0 = (pos & (DVEC - 1)) * 4;    // first column (even)
    const float ft = (float)t;

    // 10000^(-2*i/D) = 2^(i * k)
    const float k = -2.0f / (float)D_MODEL * LOG2_10000;
    float a0 = ft * exp2f((float)(i0 + 0) * k);
    float a1 = ft * exp2f((float)(i0 + 1) * k);
    float a2 = ft * exp2f((float)(i0 + 2) * k);
    float a3 = ft * exp2f((float)(i0 + 3) * k);

    float4 pe;
    pe.x = sinf(a0);   // even i -> sin
    pe.y = cosf(a1);   // odd  i -> cos
    pe.z = sinf(a2);
    pe.w = cosf(a3);

    const unsigned base = pos + g * (unsigned)(BPT * PE_VEC4);

    // Load all 8 first for max MLP, then add+store.
    float4 xv[BPT];
    #pragma unroll
    for (int b = 0; b < BPT; b++)
        xv[b] = __ldcs(&x[base + (unsigned)b * PE_VEC4]);

    #pragma unroll
    for (int b = 0; b < BPT; b++) {
        float4 o;
        o.x = xv[b].x + pe.x;
        o.y = xv[b].y + pe.y;
        o.z = xv[b].z + pe.z;
        o.w = xv[b].w + pe.w;
        __stcs(&out[base + (unsigned)b * PE_VEC4], o);
    }
}

extern "C" void kernel_launch(void* const* d_in, const int* in_sizes, int n_in,
                              void* d_out, int out_size) {
    const float4* x = (const float4*)d_in[0];
    float4* out = (float4*)d_out;
    // 8192 blocks x 256 threads = 2M threads, exact cover
    fused_pe_add_kernel<<<(PE_VEC4 / 256) * GROUPS, 256>>>(x, out);
}

// round 5
// speedup vs baseline: 1.0509x; 1.0012x over previous
#include <cuda_runtime.h>
#include <cuda_bf16.h>
#include <cstdint>

#define D_MODEL 1024
#define NUM_T   2048
#define BATCH   32

#define PE_ELEMS (NUM_T * D_MODEL)            // 2,097,152
#define PE_VEC4  (PE_ELEMS / 4)               // 524,288
#define DVEC     (D_MODEL / 4)                // 256

#define BPT     4                             // batches per thread (MLP=4, regs low)
#define GROUPS  (BATCH / BPT)                 // 8 block-groups

#define LOG2_10000 13.287712379549449f

// Fused PE+add. One thread = one unique (t, d-vec4) position x 4 batches.
// 8 block-groups (low blockIdx bits) split the 32 batches: concurrent blocks
// form contiguous streams (round-2's winning 16384-block shape) while the
// register buffer stays at 4 float4 -> higher occupancy than round 4's 40%.
__global__ void __launch_bounds__(256) fused_pe_add_kernel(const float4* __restrict__ x,
                                                           float4* __restrict__ out) {
    const unsigned g   = blockIdx.x & (GROUPS - 1u);      // batch group 0..7
    const unsigned pb  = blockIdx.x >> 3;                 // position block 0..2047
    const unsigned pos = pb * 256u + threadIdx.x;         // 0..PE_VEC4-1

    const int t  = pos >> 8;                  // timestep 0..2047
    const int i0 = (pos & (DVEC - 1)) * 4;    // first column (even)
    const float ft = (float)t;

    // 10000^(-2*i/D) = 2^(i * k)
    const float k = -2.0f / (float)D_MODEL * LOG2_10000;
    float a0 = ft * exp2f((float)(i0 + 0) * k);
    float a1 = ft * exp2f((float)(i0 + 1) * k);
    float a2 = ft * exp2f((float)(i0 + 2) * k);
    float a3 = ft * exp2f((float)(i0 + 3) * k);

    float4 pe;
    pe.x = sinf(a0);   // even i -> sin
    pe.y = cosf(a1);   // odd  i -> cos
    pe.z = sinf(a2);
    pe.w = cosf(a3);

    const unsigned base = pos + g * (unsigned)(BPT * PE_VEC4);

    // Load all 4 first (MLP=4), then add+store.
    float4 xv[BPT];
    #pragma unroll
    for (int b = 0; b < BPT; b++)
        xv[b] = __ldcs(&x[base + (unsigned)b * PE_VEC4]);

    #pragma unroll
    for (int b = 0; b < BPT; b++) {
        float4 o;
        o.x = xv[b].x + pe.x;
        o.y = xv[b].y + pe.y;
        o.z = xv[b].z + pe.z;
        o.w = xv[b].w + pe.w;
        __stcs(&out[base + (unsigned)b * PE_VEC4], o);
    }
}

extern "C" void kernel_launch(void* const* d_in, const int* in_sizes, int n_in,
                              void* d_out, int out_size) {
    const float4* x = (const float4*)d_in[0];
    float4* out = (float4*)d_out;
    // 16384 blocks x 256 threads, exact cover
    fused_pe_add_kernel<<<(PE_VEC4 / 256) * GROUPS, 256>>>(x, out);
}